// round 14
// baseline (speedup 1.0000x reference)
#include <cuda_runtime.h>
#include <math.h>

// ClusteredAttention: b=4, l=4096, d=64 fp32, labels in [0,8).
// Counting-sort by label -> perm/slab/block-table (block table built in
// parallel across 8 segment-threads). NO gather pass: the main kernel reads
// Q/K/V directly through perm (rows are 256B contiguous, coalesced per row)
// and converts to tf32 inline. Flash attention on cluster-aligned 64-query
// blocks with m16n8k8 TF32 MMAs (PADS=68 conflict-free operand LDS, hoisted
// Q fragments). Time-query split-softmax in spare grid slots; combine fused
// into the last chunk block.

#define LSEQ 4096
#define LM1  4095
#define HD   64
#define BM   64
#define BN   64
#define PADS 68
#define NTHREADS 256
#define MAXB 4
#define MAXBLK 72
#define TQ_CHUNKS 256
#define TQ_NCH    (LSEQ / TQ_CHUNKS)   // 16
#define GRIDX     (MAXBLK + TQ_NCH)    // 88

__device__ int   g_perm[MAXB * LSEQ];
__device__ int   g_slab[MAXB * LSEQ];
__device__ int4  g_btab[MAXB * MAXBLK];
__device__ int   g_nblk[MAXB];
__device__ float g_tq[MAXB * TQ_NCH * (HD + 2)];
__device__ int   g_tqcnt[MAXB];

__device__ __forceinline__ unsigned f2tf32(float v) {
    unsigned r;
    asm("cvt.rna.tf32.f32 %0, %1;" : "=r"(r) : "f"(v));
    return r;
}

__device__ __forceinline__ void mma_tf32(float c[4],
                                         unsigned a0, unsigned a1,
                                         unsigned a2, unsigned a3,
                                         unsigned b0, unsigned b1) {
    asm("mma.sync.aligned.m16n8k8.row.col.f32.tf32.tf32.f32 "
        "{%0,%1,%2,%3}, {%4,%5,%6,%7}, {%8,%9}, {%0,%1,%2,%3};"
        : "+f"(c[0]), "+f"(c[1]), "+f"(c[2]), "+f"(c[3])
        : "r"(a0), "r"(a1), "r"(a2), "r"(a3), "r"(b0), "r"(b1));
}

// ---------------------------------------------------------------------------
// Kernel A: counting sort. Coalesced strided label loads; deterministic
// (tid,k) order; block table built in parallel (8 segment-threads).
// ---------------------------------------------------------------------------
__global__ void sort_kernel(const int* __restrict__ lab32)
{
    __shared__ int cnt[8][256];
    __shared__ int ex[8][256];
    __shared__ int tot[8];
    __shared__ int segstart[8];
    __shared__ int sh_is64;

    const int b = blockIdx.x;
    const int tid = threadIdx.x;

    if (tid < 32) {
        int nz = (lab32[2 * tid + 1] != 0) ? 1 : 0;
        unsigned any = __ballot_sync(0xffffffffu, nz);
        if (tid == 0) { sh_is64 = (any == 0u); g_tqcnt[b] = 0; }
    }
    __syncthreads();
    const int is64 = sh_is64;
    const int labbase = b * LM1;

    // coalesced: element (tid,k) = original index k*256 + tid
    int mylab[16];
    int lh[8] = {0, 0, 0, 0, 0, 0, 0, 0};
    #pragma unroll
    for (int k = 0; k < 16; k++) {
        int i = k * 256 + tid;
        int l = -1;
        if (i < LM1) {
            int gi = labbase + i;
            l = lab32[is64 ? (2 * gi) : gi];
        }
        mylab[k] = l;
        #pragma unroll
        for (int c = 0; c < 8; c++) lh[c] += (l == c);
    }
    #pragma unroll
    for (int l = 0; l < 8; l++) cnt[l][tid] = lh[l];
    __syncthreads();

    {
        int w = tid >> 5, lane = tid & 31;
        int carry = 0;
        for (int c = 0; c < 8; c++) {
            int t = c * 32 + lane;
            int v = cnt[w][t];
            int x = v;
            #pragma unroll
            for (int o = 1; o < 32; o <<= 1) {
                int y = __shfl_up_sync(0xffffffffu, x, o);
                if (lane >= o) x += y;
            }
            ex[w][t] = carry + x - v;
            carry += __shfl_sync(0xffffffffu, x, 31);
        }
        if (lane == 0) tot[w] = carry;
    }
    __syncthreads();

    // ---- parallel block-table: thread l (l<8) owns segment l
    if (tid < 8) {
        int l = tid;
        int s = 0, nbo = 0;
        #pragma unroll
        for (int j = 0; j < 8; j++) {
            int t = tot[j];
            int nbl = (t + BM - 1) / BM;
            if (j < l) { s += t; nbo += nbl; }
        }
        int e = s + tot[l];
        segstart[l] = s;
        int kb = s & ~(BN - 1);
        int ke = min((e + BN - 1) & ~(BN - 1), LSEQ);
        int nb = nbo;
        for (int q0 = s; q0 < e; q0 += BM) {
            g_btab[b * MAXBLK + nb] = make_int4(q0, e, kb, ke);
            nb++;
        }
        if (l == 7) g_nblk[b] = nb;
    }
    if (tid == 8) {
        g_perm[b * LSEQ + LM1] = LM1;
        g_slab[b * LSEQ + LM1] = -2;
    }
    __syncthreads();

    // scatter in (tid,k) order; run-count via unrolled register compares
    #pragma unroll
    for (int k = 0; k < 16; k++) {
        int l = mylab[k];
        if (l >= 0) {
            int run = 0;
            #pragma unroll
            for (int k2 = 0; k2 < 16; k2++)
                if (k2 < k) run += (mylab[k2] == l);
            int pos = segstart[l] + ex[l][tid] + run;
            g_perm[b * LSEQ + pos] = k * 256 + tid;
            g_slab[b * LSEQ + pos] = l;
        }
    }
}

// ---------------------------------------------------------------------------
// Kernel B: main kernel, 256 threads, TF32 tensor-core GEMMs.
//   slot <  nblk          : block-sparse flash attention
//   nblk <= slot < nblk+16: time-query chunk; last one combines
// ---------------------------------------------------------------------------
__global__ __launch_bounds__(NTHREADS, 2)
void clustered_attn_kernel(const float* __restrict__ Q,
                           const float* __restrict__ K,
                           const float* __restrict__ V,
                           float* __restrict__ Out)
{
    extern __shared__ float sm[];

    const int b    = blockIdx.y;
    const int slot = blockIdx.x;
    const int tid  = threadIdx.x;
    const int nblk = g_nblk[b];
    const long long bbase = (long long)b * LSEQ;
    const float scale = 0.125f;

    // ===================== time-query chunk path (exact fp32) ============
    if (slot >= nblk) {
        const int c = slot - nblk;
        if (c >= TQ_NCH) return;

        float* q    = sm;
        float* p    = sm + 64;
        float* red  = sm + 320;
        float* vacc = sm + 336;
        __shared__ int amlast;

        if (tid < HD) q[tid] = Q[(bbase + LM1) * HD + tid];
        __syncthreads();

        const int j = c * TQ_CHUNKS + tid;
        const float* kr = K + (bbase + j) * HD;
        float dot = 0.0f;
        #pragma unroll
        for (int d = 0; d < HD; d += 4) {
            float4 k4 = *reinterpret_cast<const float4*>(kr + d);
            dot += q[d] * k4.x + q[d + 1] * k4.y + q[d + 2] * k4.z + q[d + 3] * k4.w;
        }
        dot *= scale;

        float m = dot;
        #pragma unroll
        for (int o = 16; o >= 1; o >>= 1)
            m = fmaxf(m, __shfl_xor_sync(0xffffffffu, m, o));
        if ((tid & 31) == 0) red[tid >> 5] = m;
        __syncthreads();
        m = red[0];
        #pragma unroll
        for (int w = 1; w < 8; w++) m = fmaxf(m, red[w]);

        float pv = __expf(dot - m);
        p[tid] = pv;

        float s = pv;
        #pragma unroll
        for (int o = 16; o >= 1; o >>= 1)
            s += __shfl_xor_sync(0xffffffffu, s, o);
        if ((tid & 31) == 0) red[8 + (tid >> 5)] = s;
        __syncthreads();
        s = red[8];
        #pragma unroll
        for (int w = 1; w < 8; w++) s += red[8 + w];

        const int d = tid & 63, h = tid >> 6;
        float a = 0.0f;
        #pragma unroll 8
        for (int jj = h * 64; jj < h * 64 + 64; jj++)
            a += p[jj] * V[(bbase + c * TQ_CHUNKS + jj) * HD + d];
        vacc[h * HD + d] = a;
        __syncthreads();

        float* out = g_tq + (b * TQ_NCH + c) * (HD + 2);
        if (tid < HD)
            out[tid] = vacc[tid] + vacc[HD + tid] + vacc[2 * HD + tid] + vacc[3 * HD + tid];
        else if (tid == HD) { out[HD] = m; out[HD + 1] = s; }
        __syncthreads();

        __threadfence();
        if (tid == 0) amlast = (atomicAdd(&g_tqcnt[b], 1) == TQ_NCH - 1);
        __syncthreads();
        if (!amlast) return;
        __threadfence();

        if (tid < HD) {
            const float* part = g_tq + b * TQ_NCH * (HD + 2);
            float M = -INFINITY;
            #pragma unroll
            for (int cc = 0; cc < TQ_NCH; cc++)
                M = fmaxf(M, part[cc * (HD + 2) + HD]);
            float stot = 0.0f, a2 = 0.0f;
            #pragma unroll
            for (int cc = 0; cc < TQ_NCH; cc++) {
                float f = __expf(part[cc * (HD + 2) + HD] - M);
                stot += part[cc * (HD + 2) + HD + 1] * f;
                a2   += part[cc * (HD + 2) + tid] * f;
            }
            Out[(bbase + LM1) * HD + tid] = a2 / stot;
        }
        return;
    }

    // ===================== attention path =====================
    float* Qs = sm;                      // [64][PADS] row-major, scaled tf32
    float* Ks = Qs + 64 * PADS;          // [64][PADS] tf32
    float* Vs = Ks + 64 * PADS;          // [64][PADS] tf32
    float* St = Vs + 64 * PADS;          // [64][PADS] scores / probs
    float* kt = St + 64 * PADS;          // [64] exact time key
    float* vt = kt + 64;                 // [64] exact time value
    float* frow_s = vt + 64;             // [64] per-row rescale
    float* ft_s   = frow_s + 64;
    float* pt_s   = ft_s + 64;
    float* li_s   = pt_s + 64;
    int*   klabs  = (int*)(li_s + 64);   // [64]
    int*   pidx   = klabs + 64;          // [64] perm of current key tile

    const unsigned* Qu = (const unsigned*)Qs;
    const unsigned* Ku = (const unsigned*)Ks;
    const unsigned* Vu = (const unsigned*)Vs;
    const unsigned* Su = (const unsigned*)St;

    const int4 blk = g_btab[b * MAXBLK + slot];
    const int q0 = blk.x, qe = blk.y, kb = blk.z, ke = blk.w;

    const int tx = tid & 15;
    const int ty = tid >> 4;
    const int lane = tid & 31;
    const int warp = tid >> 5;
    const int mw = 16 * (warp >> 1);     // warp's m-slab (0/16/32/48)
    const int nw = 32 * (warp & 1);      // warp's n-half (0/32)
    const int gid = lane >> 2;
    const int tig = lane & 3;
    const int rA0 = (mw + gid) * PADS;
    const int rA1 = (mw + gid + 8) * PADS;

    const int* perm = g_perm + b * LSEQ;
    const int* slab = g_slab + b * LSEQ;

    // ---- stage Q (row-major, scaled, tf32) directly via perm + time K/V
    #pragma unroll
    for (int idx = tid; idx < BM * HD; idx += NTHREADS) {
        int m = idx >> 6, d = idx & 63;
        int src = perm[min(q0 + m, LM1)];
        float v = Q[(bbase + src) * HD + d] * scale;
        Qs[m * PADS + d] = __uint_as_float(f2tf32(v));
    }
    if (tid < HD) kt[tid] = K[(bbase + LM1) * HD + tid];
    else if (tid < 2 * HD) vt[tid - HD] = V[(bbase + LM1) * HD + (tid - HD)];
    __syncthreads();

    // ---- hoist Q fragments (tile-invariant) into registers
    unsigned aq[8][4];
    #pragma unroll
    for (int kg = 0; kg < 8; kg++) {
        int k0 = kg * 8;
        aq[kg][0] = Qu[rA0 + k0 + tig];
        aq[kg][1] = Qu[rA1 + k0 + tig];
        aq[kg][2] = Qu[rA0 + k0 + tig + 4];
        aq[kg][3] = Qu[rA1 + k0 + tig + 4];
    }

    int qlab[4];
    #pragma unroll
    for (int i = 0; i < 4; i++) {
        int r = q0 + ty * 4 + i;
        qlab[i] = (r < qe) ? slab[r] : -3;
    }

    float mrow[4], lrow[4];
    #pragma unroll
    for (int i = 0; i < 4; i++) { mrow[i] = -INFINITY; lrow[i] = 0.0f; }

    float oc[4][4];
    #pragma unroll
    for (int ng = 0; ng < 4; ng++)
        #pragma unroll
        for (int r = 0; r < 4; r++) oc[ng][r] = 0.0f;

    for (int n0 = kb; n0 < ke; n0 += BN) {
        __syncthreads();   // prev PV reads done

        // stage this tile's perm + labels first (tiny)
        if (tid < BN) {
            pidx[tid]  = perm[n0 + tid];
            klabs[tid] = slab[n0 + tid];
        }
        __syncthreads();

        // ---- stage K/V tiles via perm (one warp per row -> coalesced 256B),
        //      tf32 conversion inline
        #pragma unroll
        for (int idx = tid; idx < BN * 32; idx += NTHREADS) {
            int n = idx >> 5, c = (idx & 31) * 2;
            long long ro = (bbase + pidx[n]) * HD + c;
            float2 kk = *(const float2*)&K[ro];
            float2 vv = *(const float2*)&V[ro];
            kk.x = __uint_as_float(f2tf32(kk.x));
            kk.y = __uint_as_float(f2tf32(kk.y));
            vv.x = __uint_as_float(f2tf32(vv.x));
            vv.y = __uint_as_float(f2tf32(vv.y));
            *(float2*)&Ks[n * PADS + c] = kk;
            *(float2*)&Vs[n * PADS + c] = vv;
        }
        __syncthreads();

        // ---- S = Q K^T via tensor cores (conflict-free B loads, PADS=68)
        float sc[4][4];
        #pragma unroll
        for (int ng = 0; ng < 4; ng++)
            #pragma unroll
            for (int r = 0; r < 4; r++) sc[ng][r] = 0.0f;

        #pragma unroll
        for (int kg = 0; kg < 8; kg++) {
            int k0 = kg * 8;
            #pragma unroll
            for (int ng = 0; ng < 4; ng++) {
                int nb = (nw + 8 * ng + gid) * PADS + k0 + tig;
                mma_tf32(sc[ng], aq[kg][0], aq[kg][1], aq[kg][2], aq[kg][3],
                         Ku[nb], Ku[nb + 4]);
            }
        }
        #pragma unroll
        for (int ng = 0; ng < 4; ng++) {
            int cbase = nw + 8 * ng + 2 * tig;
            *(float2*)&St[rA0 + cbase] = make_float2(sc[ng][0], sc[ng][1]);
            *(float2*)&St[rA1 + cbase] = make_float2(sc[ng][2], sc[ng][3]);
        }
        __syncthreads();

        // ---- mask + online softmax (scalar path on smem S)
        int klj[4];
        #pragma unroll
        for (int j = 0; j < 4; j++) klj[j] = klabs[4 * tx + j];

        #pragma unroll
        for (int i = 0; i < 4; i++) {
            int rbase = (4 * ty + i) * PADS + 4 * tx;
            float2 lo = *(const float2*)&St[rbase];
            float2 hi = *(const float2*)&St[rbase + 2];
            float s0 = (qlab[i] == klj[0]) ? lo.x : -INFINITY;
            float s1 = (qlab[i] == klj[1]) ? lo.y : -INFINITY;
            float s2 = (qlab[i] == klj[2]) ? hi.x : -INFINITY;
            float s3 = (qlab[i] == klj[3]) ? hi.y : -INFINITY;

            float tm = fmaxf(fmaxf(s0, s1), fmaxf(s2, s3));
            #pragma unroll
            for (int o = 8; o >= 1; o >>= 1)
                tm = fmaxf(tm, __shfl_xor_sync(0xffffffffu, tm, o));

            float newm = fmaxf(mrow[i], tm);
            float mref = (newm == -INFINITY) ? 0.0f : newm;
            float fi = __expf(mrow[i] - mref);

            float p0 = __expf(s0 - mref);
            float p1 = __expf(s1 - mref);
            float p2 = __expf(s2 - mref);
            float p3 = __expf(s3 - mref);
            float rs = (p0 + p1) + (p2 + p3);
            #pragma unroll
            for (int o = 8; o >= 1; o >>= 1)
                rs += __shfl_xor_sync(0xffffffffu, rs, o);

            lrow[i] = lrow[i] * fi + rs;
            mrow[i] = newm;

            *(float2*)&St[rbase] = make_float2(__uint_as_float(f2tf32(p0)),
                                               __uint_as_float(f2tf32(p1)));
            *(float2*)&St[rbase + 2] = make_float2(__uint_as_float(f2tf32(p2)),
                                                   __uint_as_float(f2tf32(p3)));
            if (tx == 0) frow_s[4 * ty + i] = fi;
        }
        __syncthreads();

        // ---- O = O*f + P V via tensor cores (conflict-free V loads)
        {
            float f0 = frow_s[mw + gid];
            float f1 = frow_s[mw + gid + 8];
            #pragma unroll
            for (int ng = 0; ng < 4; ng++) {
                oc[ng][0] *= f0; oc[ng][1] *= f0;
                oc[ng][2] *= f1; oc[ng][3] *= f1;
            }
        }
        #pragma unroll
        for (int kg = 0; kg < 8; kg++) {
            int k0 = kg * 8;
            unsigned a0 = Su[rA0 + k0 + tig];
            unsigned a1 = Su[rA1 + k0 + tig];
            unsigned a2 = Su[rA0 + k0 + tig + 4];
            unsigned a3 = Su[rA1 + k0 + tig + 4];
            #pragma unroll
            for (int ng = 0; ng < 4; ng++) {
                int vb = (k0 + tig) * PADS + nw + 8 * ng + gid;
                mma_tf32(oc[ng], a0, a1, a2, a3, Vu[vb], Vu[vb + 4 * PADS]);
            }
        }
    }

    // ---- time key column (exact fp32)
    #pragma unroll
    for (int i = 0; i < 4; i++) {
        int row = 4 * ty + i;
        float part = 0.0f;
        #pragma unroll
        for (int jj = 0; jj < 4; jj++)
            part += Qs[row * PADS + 4 * tx + jj] * kt[4 * tx + jj];
        #pragma unroll
        for (int o = 8; o >= 1; o >>= 1)
            part += __shfl_xor_sync(0xffffffffu, part, o);
        float st = part;   // Q pre-scaled

        float newm = fmaxf(mrow[i], st);
        float f = __expf(mrow[i] - newm);
        float p = __expf(st - newm);
        lrow[i] = lrow[i] * f + p;
        mrow[i] = newm;
        if (tx == 0) {
            ft_s[row] = f;
            pt_s[row] = p;
            li_s[row] = 1.0f / lrow[i];
        }
    }
    __syncthreads();

    // ---- epilogue on O frags: time-key add, normalize, scatter
    {
        float f0 = ft_s[mw + gid],     p0 = pt_s[mw + gid],     i0 = li_s[mw + gid];
        float f1 = ft_s[mw + gid + 8], p1 = pt_s[mw + gid + 8], i1 = li_s[mw + gid + 8];
        int r0 = q0 + mw + gid;
        int r1 = r0 + 8;
        bool good0 = r0 < qe, good1 = r1 < qe;
        long long o0 = good0 ? (bbase + perm[r0]) * HD : 0;
        long long o1 = good1 ? (bbase + perm[r1]) * HD : 0;

        #pragma unroll
        for (int ng = 0; ng < 4; ng++) {
            int col = nw + 8 * ng + 2 * tig;
            float x0 = (oc[ng][0] * f0 + p0 * vt[col])     * i0;
            float x1 = (oc[ng][1] * f0 + p0 * vt[col + 1]) * i0;
            float x2 = (oc[ng][2] * f1 + p1 * vt[col])     * i1;
            float x3 = (oc[ng][3] * f1 + p1 * vt[col + 1]) * i1;
            if (good0) *(float2*)&Out[o0 + col] = make_float2(x0, x1);
            if (good1) *(float2*)&Out[o1 + col] = make_float2(x2, x3);
        }
    }
}

// ---------------------------------------------------------------------------
extern "C" void kernel_launch(void* const* d_in, const int* in_sizes, int n_in,
                              void* d_out, int out_size)
{
    const float* Q = (const float*)d_in[0];
    const float* K = (const float*)d_in[1];
    const float* V = (const float*)d_in[2];
    const int* lab = (const int*)d_in[3];
    float* Out = (float*)d_out;

    const int B = in_sizes[0] / (LSEQ * HD);

    sort_kernel<<<B, 256>>>(lab);

    const int smem_bytes = (4 * 64 * PADS + 6 * 64) * (int)sizeof(float)
                           + 2 * 64 * (int)sizeof(int);
    cudaFuncSetAttribute(clustered_attn_kernel,
                         cudaFuncAttributeMaxDynamicSharedMemorySize, smem_bytes);
    dim3 grid(GRIDX, B);
    clustered_attn_kernel<<<grid, NTHREADS, smem_bytes>>>(Q, K, V, Out);
}

// round 15
// speedup vs baseline: 1.1686x; 1.1686x over previous
#include <cuda_runtime.h>
#include <math.h>

// ClusteredAttention: b=4, l=4096, d=64 fp32, labels in [0,8).
// Counting-sort by label (parallel block-table) -> perm/slab/btab; gather
// K/V cluster-contiguous with tf32 pre-conversion; flash-attend cluster-
// aligned 64-query blocks with m16n8k8 TF32 MMAs (PADS=68 conflict-free
// operand LDS, hoisted Q fragments). 1D batch-major grid interleave puts all
// attention blocks in wave 1. Time-query split-softmax in tail slots;
// combine fused into the last chunk block.

#define LSEQ 4096
#define LM1  4095
#define HD   64
#define BM   64
#define BN   64
#define PADS 68
#define NTHREADS 256
#define MAXB 4
#define MAXBLK 72
#define TQ_CHUNKS 256
#define TQ_NCH    (LSEQ / TQ_CHUNKS)   // 16
#define GRIDX     (MAXBLK + TQ_NCH)    // 88

__device__ float g_Ks[MAXB * LSEQ * HD];   // tf32-rounded
__device__ float g_Vs[MAXB * LSEQ * HD];   // tf32-rounded
__device__ int   g_perm[MAXB * LSEQ];
__device__ int   g_slab[MAXB * LSEQ];
__device__ int4  g_btab[MAXB * MAXBLK];
__device__ int   g_nblk[MAXB];
__device__ float g_tq[MAXB * TQ_NCH * (HD + 2)];
__device__ int   g_tqcnt[MAXB];

__device__ __forceinline__ unsigned f2tf32(float v) {
    unsigned r;
    asm("cvt.rna.tf32.f32 %0, %1;" : "=r"(r) : "f"(v));
    return r;
}

__device__ __forceinline__ void mma_tf32(float c[4],
                                         unsigned a0, unsigned a1,
                                         unsigned a2, unsigned a3,
                                         unsigned b0, unsigned b1) {
    asm("mma.sync.aligned.m16n8k8.row.col.f32.tf32.tf32.f32 "
        "{%0,%1,%2,%3}, {%4,%5,%6,%7}, {%8,%9}, {%0,%1,%2,%3};"
        : "+f"(c[0]), "+f"(c[1]), "+f"(c[2]), "+f"(c[3])
        : "r"(a0), "r"(a1), "r"(a2), "r"(a3), "r"(b0), "r"(b1));
}

// ---------------------------------------------------------------------------
// Kernel A: counting sort + parallel block table.
// ---------------------------------------------------------------------------
__global__ void sort_kernel(const int* __restrict__ lab32)
{
    __shared__ int cnt[8][256];
    __shared__ int ex[8][256];
    __shared__ int tot[8];
    __shared__ int segstart[8];
    __shared__ int sh_is64;

    const int b = blockIdx.x;
    const int tid = threadIdx.x;

    if (tid < 32) {
        int nz = (lab32[2 * tid + 1] != 0) ? 1 : 0;
        unsigned any = __ballot_sync(0xffffffffu, nz);
        if (tid == 0) { sh_is64 = (any == 0u); g_tqcnt[b] = 0; }
    }
    __syncthreads();
    const int is64 = sh_is64;
    const int labbase = b * LM1;

    // coalesced: element (tid,k) = original index k*256 + tid
    int mylab[16];
    int lh[8] = {0, 0, 0, 0, 0, 0, 0, 0};
    #pragma unroll
    for (int k = 0; k < 16; k++) {
        int i = k * 256 + tid;
        int l = -1;
        if (i < LM1) {
            int gi = labbase + i;
            l = lab32[is64 ? (2 * gi) : gi];
        }
        mylab[k] = l;
        #pragma unroll
        for (int c = 0; c < 8; c++) lh[c] += (l == c);
    }
    #pragma unroll
    for (int l = 0; l < 8; l++) cnt[l][tid] = lh[l];
    __syncthreads();

    {
        int w = tid >> 5, lane = tid & 31;
        int carry = 0;
        for (int c = 0; c < 8; c++) {
            int t = c * 32 + lane;
            int v = cnt[w][t];
            int x = v;
            #pragma unroll
            for (int o = 1; o < 32; o <<= 1) {
                int y = __shfl_up_sync(0xffffffffu, x, o);
                if (lane >= o) x += y;
            }
            ex[w][t] = carry + x - v;
            carry += __shfl_sync(0xffffffffu, x, 31);
        }
        if (lane == 0) tot[w] = carry;
    }
    __syncthreads();

    // ---- parallel block-table: thread l (l<8) owns segment l
    if (tid < 8) {
        int l = tid;
        int s = 0, nbo = 0;
        #pragma unroll
        for (int j = 0; j < 8; j++) {
            int t = tot[j];
            int nbl = (t + BM - 1) / BM;
            if (j < l) { s += t; nbo += nbl; }
        }
        int e = s + tot[l];
        segstart[l] = s;
        int kb = s & ~(BN - 1);
        int ke = min((e + BN - 1) & ~(BN - 1), LSEQ);
        int nb = nbo;
        for (int q0 = s; q0 < e; q0 += BM) {
            g_btab[b * MAXBLK + nb] = make_int4(q0, e, kb, ke);
            nb++;
        }
        if (l == 7) g_nblk[b] = nb;
    }
    if (tid == 8) {
        g_perm[b * LSEQ + LM1] = LM1;
        g_slab[b * LSEQ + LM1] = -2;
    }
    __syncthreads();

    // scatter in (tid,k) order; run-count via unrolled register compares
    #pragma unroll
    for (int k = 0; k < 16; k++) {
        int l = mylab[k];
        if (l >= 0) {
            int run = 0;
            #pragma unroll
            for (int k2 = 0; k2 < 16; k2++)
                if (k2 < k) run += (mylab[k2] == l);
            int pos = segstart[l] + ex[l][tid] + run;
            g_perm[b * LSEQ + pos] = k * 256 + tid;
            g_slab[b * LSEQ + pos] = l;
        }
    }
}

// ---------------------------------------------------------------------------
// Kernel B: gather K/V rows into sorted order + tf32 pre-conversion.
// ---------------------------------------------------------------------------
__global__ void gather_kernel(const float* __restrict__ K,
                              const float* __restrict__ V)
{
    int idx = blockIdx.x * blockDim.x + threadIdx.x;
    int r = idx >> 4;
    int c = idx & 15;
    int b = r >> 12;
    int src = g_perm[r];
    long long so = ((long long)(b << 12) + src) * 16 + c;
    float4 k4 = ((const float4*)K)[so];
    float4 v4 = ((const float4*)V)[so];
    k4.x = __uint_as_float(f2tf32(k4.x));
    k4.y = __uint_as_float(f2tf32(k4.y));
    k4.z = __uint_as_float(f2tf32(k4.z));
    k4.w = __uint_as_float(f2tf32(k4.w));
    v4.x = __uint_as_float(f2tf32(v4.x));
    v4.y = __uint_as_float(f2tf32(v4.y));
    v4.z = __uint_as_float(f2tf32(v4.z));
    v4.w = __uint_as_float(f2tf32(v4.w));
    ((float4*)g_Ks)[r * 16 + c] = k4;
    ((float4*)g_Vs)[r * 16 + c] = v4;
}

// ---------------------------------------------------------------------------
// Kernel C: main kernel, 256 threads, TF32 tensor-core GEMMs.
// 1D grid, batch-major: bid -> (b = bid % B, slot = bid / B) so all
// attention blocks (slot < nblk <= 72) schedule before tq chunks.
// ---------------------------------------------------------------------------
__global__ __launch_bounds__(NTHREADS, 2)
void clustered_attn_kernel(const float* __restrict__ Q,
                           const float* __restrict__ K,
                           const float* __restrict__ V,
                           float* __restrict__ Out,
                           int B)
{
    extern __shared__ float sm[];

    const int b    = blockIdx.x % B;
    const int slot = blockIdx.x / B;
    const int tid  = threadIdx.x;
    const int nblk = g_nblk[b];
    const long long bbase = (long long)b * LSEQ;
    const float scale = 0.125f;

    // ===================== time-query chunk path (exact fp32) ============
    if (slot >= nblk) {
        const int c = slot - nblk;
        if (c >= TQ_NCH) return;

        float* q    = sm;
        float* p    = sm + 64;
        float* red  = sm + 320;
        float* vacc = sm + 336;
        __shared__ int amlast;

        if (tid < HD) q[tid] = Q[(bbase + LM1) * HD + tid];
        __syncthreads();

        const int j = c * TQ_CHUNKS + tid;
        const float* kr = K + (bbase + j) * HD;
        float dot = 0.0f;
        #pragma unroll
        for (int d = 0; d < HD; d += 4) {
            float4 k4 = *reinterpret_cast<const float4*>(kr + d);
            dot += q[d] * k4.x + q[d + 1] * k4.y + q[d + 2] * k4.z + q[d + 3] * k4.w;
        }
        dot *= scale;

        float m = dot;
        #pragma unroll
        for (int o = 16; o >= 1; o >>= 1)
            m = fmaxf(m, __shfl_xor_sync(0xffffffffu, m, o));
        if ((tid & 31) == 0) red[tid >> 5] = m;
        __syncthreads();
        m = red[0];
        #pragma unroll
        for (int w = 1; w < 8; w++) m = fmaxf(m, red[w]);

        float pv = __expf(dot - m);
        p[tid] = pv;

        float s = pv;
        #pragma unroll
        for (int o = 16; o >= 1; o >>= 1)
            s += __shfl_xor_sync(0xffffffffu, s, o);
        if ((tid & 31) == 0) red[8 + (tid >> 5)] = s;
        __syncthreads();
        s = red[8];
        #pragma unroll
        for (int w = 1; w < 8; w++) s += red[8 + w];

        const int d = tid & 63, h = tid >> 6;
        float a = 0.0f;
        #pragma unroll 8
        for (int jj = h * 64; jj < h * 64 + 64; jj++)
            a += p[jj] * V[(bbase + c * TQ_CHUNKS + jj) * HD + d];
        vacc[h * HD + d] = a;
        __syncthreads();

        float* out = g_tq + (b * TQ_NCH + c) * (HD + 2);
        if (tid < HD)
            out[tid] = vacc[tid] + vacc[HD + tid] + vacc[2 * HD + tid] + vacc[3 * HD + tid];
        else if (tid == HD) { out[HD] = m; out[HD + 1] = s; }
        __syncthreads();

        __threadfence();
        if (tid == 0) amlast = (atomicAdd(&g_tqcnt[b], 1) == TQ_NCH - 1);
        __syncthreads();
        if (!amlast) return;
        __threadfence();

        if (tid < HD) {
            const float* part = g_tq + b * TQ_NCH * (HD + 2);
            float M = -INFINITY;
            #pragma unroll
            for (int cc = 0; cc < TQ_NCH; cc++)
                M = fmaxf(M, part[cc * (HD + 2) + HD]);
            float stot = 0.0f, a2 = 0.0f;
            #pragma unroll
            for (int cc = 0; cc < TQ_NCH; cc++) {
                float f = __expf(part[cc * (HD + 2) + HD] - M);
                stot += part[cc * (HD + 2) + HD + 1] * f;
                a2   += part[cc * (HD + 2) + tid] * f;
            }
            Out[(bbase + LM1) * HD + tid] = a2 / stot;
        }
        return;
    }

    // ===================== attention path =====================
    float* Qs = sm;                      // [64][PADS] row-major, scaled tf32
    float* Ks = Qs + 64 * PADS;          // [64][PADS] tf32
    float* Vs = Ks + 64 * PADS;          // [64][PADS] tf32
    float* St = Vs + 64 * PADS;          // [64][PADS] scores / probs
    float* kt = St + 64 * PADS;          // [64] exact time key
    float* vt = kt + 64;                 // [64] exact time value
    float* frow_s = vt + 64;             // [64] per-row rescale
    float* ft_s   = frow_s + 64;
    float* pt_s   = ft_s + 64;
    float* li_s   = pt_s + 64;
    int*   klabs  = (int*)(li_s + 64);   // [64]

    const unsigned* Qu = (const unsigned*)Qs;
    const unsigned* Ku = (const unsigned*)Ks;
    const unsigned* Vu = (const unsigned*)Vs;
    const unsigned* Su = (const unsigned*)St;

    const int4 blk = g_btab[b * MAXBLK + slot];
    const int q0 = blk.x, qe = blk.y, kb = blk.z, ke = blk.w;

    const int tx = tid & 15;
    const int ty = tid >> 4;
    const int lane = tid & 31;
    const int warp = tid >> 5;
    const int mw = 16 * (warp >> 1);     // warp's m-slab (0/16/32/48)
    const int nw = 32 * (warp & 1);      // warp's n-half (0/32)
    const int gid = lane >> 2;
    const int tig = lane & 3;
    const int rA0 = (mw + gid) * PADS;
    const int rA1 = (mw + gid + 8) * PADS;

    const int* perm = g_perm + b * LSEQ;
    const int* slab = g_slab + b * LSEQ;
    const float* Kb = g_Ks + b * LSEQ * HD;
    const float* Vb = g_Vs + b * LSEQ * HD;

    // ---- stage Q (row-major, scaled, tf32) + exact time K/V
    #pragma unroll
    for (int idx = tid; idx < BM * HD; idx += NTHREADS) {
        int m = idx >> 6, d = idx & 63;
        int src = perm[min(q0 + m, LM1)];
        float v = Q[(bbase + src) * HD + d] * scale;
        Qs[m * PADS + d] = __uint_as_float(f2tf32(v));
    }
    if (tid < HD) kt[tid] = K[(bbase + LM1) * HD + tid];
    else if (tid < 2 * HD) vt[tid - HD] = V[(bbase + LM1) * HD + (tid - HD)];
    __syncthreads();

    // ---- hoist Q fragments (tile-invariant) into registers
    unsigned aq[8][4];
    #pragma unroll
    for (int kg = 0; kg < 8; kg++) {
        int k0 = kg * 8;
        aq[kg][0] = Qu[rA0 + k0 + tig];
        aq[kg][1] = Qu[rA1 + k0 + tig];
        aq[kg][2] = Qu[rA0 + k0 + tig + 4];
        aq[kg][3] = Qu[rA1 + k0 + tig + 4];
    }

    int qlab[4];
    #pragma unroll
    for (int i = 0; i < 4; i++) {
        int r = q0 + ty * 4 + i;
        qlab[i] = (r < qe) ? slab[r] : -3;
    }

    float mrow[4], lrow[4];
    #pragma unroll
    for (int i = 0; i < 4; i++) { mrow[i] = -INFINITY; lrow[i] = 0.0f; }

    float oc[4][4];
    #pragma unroll
    for (int ng = 0; ng < 4; ng++)
        #pragma unroll
        for (int r = 0; r < 4; r++) oc[ng][r] = 0.0f;

    for (int n0 = kb; n0 < ke; n0 += BN) {
        __syncthreads();   // prev PV reads done

        // ---- stage K/V tiles (row-major float2 copy; already tf32)
        #pragma unroll
        for (int idx = tid; idx < BN * 32; idx += NTHREADS) {
            int n = idx >> 5, c = (idx & 31) * 2;
            *(float2*)&Ks[n * PADS + c] = *(const float2*)&Kb[(n0 + n) * HD + c];
            *(float2*)&Vs[n * PADS + c] = *(const float2*)&Vb[(n0 + n) * HD + c];
        }
        if (tid < BN) klabs[tid] = slab[n0 + tid];
        __syncthreads();

        // ---- S = Q K^T via tensor cores (conflict-free B loads, PADS=68)
        float sc[4][4];
        #pragma unroll
        for (int ng = 0; ng < 4; ng++)
            #pragma unroll
            for (int r = 0; r < 4; r++) sc[ng][r] = 0.0f;

        #pragma unroll
        for (int kg = 0; kg < 8; kg++) {
            int k0 = kg * 8;
            #pragma unroll
            for (int ng = 0; ng < 4; ng++) {
                int nb = (nw + 8 * ng + gid) * PADS + k0 + tig;
                mma_tf32(sc[ng], aq[kg][0], aq[kg][1], aq[kg][2], aq[kg][3],
                         Ku[nb], Ku[nb + 4]);
            }
        }
        #pragma unroll
        for (int ng = 0; ng < 4; ng++) {
            int cbase = nw + 8 * ng + 2 * tig;
            *(float2*)&St[rA0 + cbase] = make_float2(sc[ng][0], sc[ng][1]);
            *(float2*)&St[rA1 + cbase] = make_float2(sc[ng][2], sc[ng][3]);
        }
        __syncthreads();

        // ---- mask + online softmax (scalar path on smem S)
        int klj[4];
        #pragma unroll
        for (int j = 0; j < 4; j++) klj[j] = klabs[4 * tx + j];

        #pragma unroll
        for (int i = 0; i < 4; i++) {
            int rbase = (4 * ty + i) * PADS + 4 * tx;
            float2 lo = *(const float2*)&St[rbase];
            float2 hi = *(const float2*)&St[rbase + 2];
            float s0 = (qlab[i] == klj[0]) ? lo.x : -INFINITY;
            float s1 = (qlab[i] == klj[1]) ? lo.y : -INFINITY;
            float s2 = (qlab[i] == klj[2]) ? hi.x : -INFINITY;
            float s3 = (qlab[i] == klj[3]) ? hi.y : -INFINITY;

            float tm = fmaxf(fmaxf(s0, s1), fmaxf(s2, s3));
            #pragma unroll
            for (int o = 8; o >= 1; o >>= 1)
                tm = fmaxf(tm, __shfl_xor_sync(0xffffffffu, tm, o));

            float newm = fmaxf(mrow[i], tm);
            float mref = (newm == -INFINITY) ? 0.0f : newm;
            float fi = __expf(mrow[i] - mref);

            float p0 = __expf(s0 - mref);
            float p1 = __expf(s1 - mref);
            float p2 = __expf(s2 - mref);
            float p3 = __expf(s3 - mref);
            float rs = (p0 + p1) + (p2 + p3);
            #pragma unroll
            for (int o = 8; o >= 1; o >>= 1)
                rs += __shfl_xor_sync(0xffffffffu, rs, o);

            lrow[i] = lrow[i] * fi + rs;
            mrow[i] = newm;

            *(float2*)&St[rbase] = make_float2(__uint_as_float(f2tf32(p0)),
                                               __uint_as_float(f2tf32(p1)));
            *(float2*)&St[rbase + 2] = make_float2(__uint_as_float(f2tf32(p2)),
                                                   __uint_as_float(f2tf32(p3)));
            if (tx == 0) frow_s[4 * ty + i] = fi;
        }
        __syncthreads();

        // ---- O = O*f + P V via tensor cores (conflict-free V loads)
        {
            float f0 = frow_s[mw + gid];
            float f1 = frow_s[mw + gid + 8];
            #pragma unroll
            for (int ng = 0; ng < 4; ng++) {
                oc[ng][0] *= f0; oc[ng][1] *= f0;
                oc[ng][2] *= f1; oc[ng][3] *= f1;
            }
        }
        #pragma unroll
        for (int kg = 0; kg < 8; kg++) {
            int k0 = kg * 8;
            unsigned a0 = Su[rA0 + k0 + tig];
            unsigned a1 = Su[rA1 + k0 + tig];
            unsigned a2 = Su[rA0 + k0 + tig + 4];
            unsigned a3 = Su[rA1 + k0 + tig + 4];
            #pragma unroll
            for (int ng = 0; ng < 4; ng++) {
                int vb = (k0 + tig) * PADS + nw + 8 * ng + gid;
                mma_tf32(oc[ng], a0, a1, a2, a3, Vu[vb], Vu[vb + 4 * PADS]);
            }
        }
    }

    // ---- time key column (exact fp32)
    #pragma unroll
    for (int i = 0; i < 4; i++) {
        int row = 4 * ty + i;
        float part = 0.0f;
        #pragma unroll
        for (int jj = 0; jj < 4; jj++)
            part += Qs[row * PADS + 4 * tx + jj] * kt[4 * tx + jj];
        #pragma unroll
        for (int o = 8; o >= 1; o >>= 1)
            part += __shfl_xor_sync(0xffffffffu, part, o);
        float st = part;   // Q pre-scaled

        float newm = fmaxf(mrow[i], st);
        float f = __expf(mrow[i] - newm);
        float p = __expf(st - newm);
        lrow[i] = lrow[i] * f + p;
        mrow[i] = newm;
        if (tx == 0) {
            ft_s[row] = f;
            pt_s[row] = p;
            li_s[row] = 1.0f / lrow[i];
        }
    }
    __syncthreads();

    // ---- epilogue on O frags: time-key add, normalize, scatter
    {
        float f0 = ft_s[mw + gid],     p0 = pt_s[mw + gid],     i0 = li_s[mw + gid];
        float f1 = ft_s[mw + gid + 8], p1 = pt_s[mw + gid + 8], i1 = li_s[mw + gid + 8];
        int r0 = q0 + mw + gid;
        int r1 = r0 + 8;
        bool good0 = r0 < qe, good1 = r1 < qe;
        long long o0 = good0 ? (bbase + perm[r0]) * HD : 0;
        long long o1 = good1 ? (bbase + perm[r1]) * HD : 0;

        #pragma unroll
        for (int ng = 0; ng < 4; ng++) {
            int col = nw + 8 * ng + 2 * tig;
            float x0 = (oc[ng][0] * f0 + p0 * vt[col])     * i0;
            float x1 = (oc[ng][1] * f0 + p0 * vt[col + 1]) * i0;
            float x2 = (oc[ng][2] * f1 + p1 * vt[col])     * i1;
            float x3 = (oc[ng][3] * f1 + p1 * vt[col + 1]) * i1;
            if (good0) *(float2*)&Out[o0 + col] = make_float2(x0, x1);
            if (good1) *(float2*)&Out[o1 + col] = make_float2(x2, x3);
        }
    }
}

// ---------------------------------------------------------------------------
extern "C" void kernel_launch(void* const* d_in, const int* in_sizes, int n_in,
                              void* d_out, int out_size)
{
    const float* Q = (const float*)d_in[0];
    const float* K = (const float*)d_in[1];
    const float* V = (const float*)d_in[2];
    const int* lab = (const int*)d_in[3];
    float* Out = (float*)d_out;

    const int B = in_sizes[0] / (LSEQ * HD);

    sort_kernel<<<B, 256>>>(lab);
    gather_kernel<<<B * 256, 256>>>(K, V);

    const int smem_bytes = (4 * 64 * PADS + 7 * 64) * (int)sizeof(float)
                           + 64 * (int)sizeof(int);
    cudaFuncSetAttribute(clustered_attn_kernel,
                         cudaFuncAttributeMaxDynamicSharedMemorySize, smem_bytes);
    clustered_attn_kernel<<<GRIDX * B, NTHREADS, smem_bytes>>>(Q, K, V, Out, B);
}

// round 17
// speedup vs baseline: 1.2492x; 1.0690x over previous
#include <cuda_runtime.h>
#include <math.h>

// ClusteredAttention: b=4, l=4096, d=64 fp32, labels in [0,8).
// Counting-sort by label (smem-staged scatter in DYNAMIC shared + coalesced
// writeout, parallel block-table, EXACT key ranges) -> perm/slab/btab;
// gather K/V cluster-contiguous with tf32 pre-conversion; flash-attend
// cluster-aligned 64-query blocks with m16n8k8 TF32 MMAs (PADS=68 conflict-
// free operand LDS, hoisted Q fragments). 1D batch-major grid puts all
// attention blocks in wave 1. Time-query split-softmax in tail slots;
// combine fused into last chunk.

#define LSEQ 4096
#define LM1  4095
#define HD   64
#define BM   64
#define BN   64
#define PADS 68
#define NTHREADS 256
#define MAXB 4
#define MAXBLK 72
#define TQ_CHUNKS 256
#define TQ_NCH    (LSEQ / TQ_CHUNKS)   // 16
#define GRIDX     (MAXBLK + TQ_NCH)    // 88

__device__ float g_Ks[MAXB * LSEQ * HD];   // tf32-rounded
__device__ float g_Vs[MAXB * LSEQ * HD];   // tf32-rounded
__device__ int   g_perm[MAXB * LSEQ];
__device__ int   g_slab[MAXB * LSEQ];
__device__ int4  g_btab[MAXB * MAXBLK];
__device__ int   g_nblk[MAXB];
__device__ float g_tq[MAXB * TQ_NCH * (HD + 2)];
__device__ int   g_tqcnt[MAXB];

__device__ __forceinline__ unsigned f2tf32(float v) {
    unsigned r;
    asm("cvt.rna.tf32.f32 %0, %1;" : "=r"(r) : "f"(v));
    return r;
}

__device__ __forceinline__ void mma_tf32(float c[4],
                                         unsigned a0, unsigned a1,
                                         unsigned a2, unsigned a3,
                                         unsigned b0, unsigned b1) {
    asm("mma.sync.aligned.m16n8k8.row.col.f32.tf32.tf32.f32 "
        "{%0,%1,%2,%3}, {%4,%5,%6,%7}, {%8,%9}, {%0,%1,%2,%3};"
        : "+f"(c[0]), "+f"(c[1]), "+f"(c[2]), "+f"(c[3])
        : "r"(a0), "r"(a1), "r"(a2), "r"(a3), "r"(b0), "r"(b1));
}

// ---------------------------------------------------------------------------
// Kernel A: counting sort. Scatter into dynamic SMEM, coalesced writeout.
// Exact (unaligned) key ranges in btab. Dynamic smem: 2*LSEQ ints = 32KB.
// ---------------------------------------------------------------------------
__global__ void sort_kernel(const int* __restrict__ lab32)
{
    extern __shared__ int dysm[];
    int* sperm = dysm;          // [LSEQ]
    int* sslab = dysm + LSEQ;   // [LSEQ]

    __shared__ int cnt[8][256];
    __shared__ int ex[8][256];
    __shared__ int tot[8];
    __shared__ int segstart[8];
    __shared__ int sh_is64;

    const int b = blockIdx.x;
    const int tid = threadIdx.x;

    if (tid < 32) {
        int nz = (lab32[2 * tid + 1] != 0) ? 1 : 0;
        unsigned any = __ballot_sync(0xffffffffu, nz);
        if (tid == 0) { sh_is64 = (any == 0u); g_tqcnt[b] = 0; }
    }
    __syncthreads();
    const int is64 = sh_is64;
    const int labbase = b * LM1;

    // coalesced loads: element (tid,k) = original index k*256 + tid
    int mylab[16];
    int lh[8] = {0, 0, 0, 0, 0, 0, 0, 0};
    #pragma unroll
    for (int k = 0; k < 16; k++) {
        int i = k * 256 + tid;
        int l = -1;
        if (i < LM1) {
            int gi = labbase + i;
            l = lab32[is64 ? (2 * gi) : gi];
        }
        mylab[k] = l;
        #pragma unroll
        for (int c = 0; c < 8; c++) lh[c] += (l == c);
    }
    #pragma unroll
    for (int l = 0; l < 8; l++) cnt[l][tid] = lh[l];
    __syncthreads();

    {
        int w = tid >> 5, lane = tid & 31;
        int carry = 0;
        for (int c = 0; c < 8; c++) {
            int t = c * 32 + lane;
            int v = cnt[w][t];
            int x = v;
            #pragma unroll
            for (int o = 1; o < 32; o <<= 1) {
                int y = __shfl_up_sync(0xffffffffu, x, o);
                if (lane >= o) x += y;
            }
            ex[w][t] = carry + x - v;
            carry += __shfl_sync(0xffffffffu, x, 31);
        }
        if (lane == 0) tot[w] = carry;
    }
    __syncthreads();

    // ---- parallel block-table: thread l (l<8) owns segment l (EXACT ranges)
    if (tid < 8) {
        int l = tid;
        int s = 0, nbo = 0;
        #pragma unroll
        for (int j = 0; j < 8; j++) {
            int t = tot[j];
            int nbl = (t + BM - 1) / BM;
            if (j < l) { s += t; nbo += nbl; }
        }
        int e = s + tot[l];
        segstart[l] = s;
        int kb = s;                                   // exact start
        int ke = s + ((e - s + BN - 1) / BN) * BN;    // exact tile count
        int nb = nbo;
        for (int q0 = s; q0 < e; q0 += BM) {
            g_btab[b * MAXBLK + nb] = make_int4(q0, e, kb, ke);
            nb++;
        }
        if (l == 7) g_nblk[b] = nb;
    }
    if (tid == 8) {
        sperm[LM1] = LM1;
        sslab[LM1] = -2;
    }
    __syncthreads();

    // scatter into SMEM (cheap), run-count via unrolled register compares
    #pragma unroll
    for (int k = 0; k < 16; k++) {
        int l = mylab[k];
        if (l >= 0) {
            int run = 0;
            #pragma unroll
            for (int k2 = 0; k2 < 16; k2++)
                if (k2 < k) run += (mylab[k2] == l);
            int pos = segstart[l] + ex[l][tid] + run;
            sperm[pos] = k * 256 + tid;
            sslab[pos] = l;
        }
    }
    __syncthreads();

    // coalesced writeout (int4-wide)
    #pragma unroll
    for (int k = 0; k < LSEQ / (NTHREADS * 4); k++) {
        int i = (k * NTHREADS + tid) * 4;
        *(int4*)&g_perm[b * LSEQ + i] = *(const int4*)&sperm[i];
        *(int4*)&g_slab[b * LSEQ + i] = *(const int4*)&sslab[i];
    }
}

// ---------------------------------------------------------------------------
// Kernel B: gather K/V rows into sorted order + tf32 pre-conversion.
// ---------------------------------------------------------------------------
__global__ void gather_kernel(const float* __restrict__ K,
                              const float* __restrict__ V)
{
    int idx = blockIdx.x * blockDim.x + threadIdx.x;
    int r = idx >> 4;
    int c = idx & 15;
    int b = r >> 12;
    int src = g_perm[r];
    long long so = ((long long)(b << 12) + src) * 16 + c;
    float4 k4 = ((const float4*)K)[so];
    float4 v4 = ((const float4*)V)[so];
    k4.x = __uint_as_float(f2tf32(k4.x));
    k4.y = __uint_as_float(f2tf32(k4.y));
    k4.z = __uint_as_float(f2tf32(k4.z));
    k4.w = __uint_as_float(f2tf32(k4.w));
    v4.x = __uint_as_float(f2tf32(v4.x));
    v4.y = __uint_as_float(f2tf32(v4.y));
    v4.z = __uint_as_float(f2tf32(v4.z));
    v4.w = __uint_as_float(f2tf32(v4.w));
    ((float4*)g_Ks)[r * 16 + c] = k4;
    ((float4*)g_Vs)[r * 16 + c] = v4;
}

// ---------------------------------------------------------------------------
// Kernel C: main kernel, 256 threads, TF32 tensor-core GEMMs.
// ---------------------------------------------------------------------------
__global__ __launch_bounds__(NTHREADS, 2)
void clustered_attn_kernel(const float* __restrict__ Q,
                           const float* __restrict__ K,
                           const float* __restrict__ V,
                           float* __restrict__ Out,
                           int B)
{
    extern __shared__ float sm[];

    const int b    = blockIdx.x % B;
    const int slot = blockIdx.x / B;
    const int tid  = threadIdx.x;
    const int nblk = g_nblk[b];
    const long long bbase = (long long)b * LSEQ;
    const float scale = 0.125f;

    // ===================== time-query chunk path (exact fp32) ============
    if (slot >= nblk) {
        const int c = slot - nblk;
        if (c >= TQ_NCH) return;

        float* q    = sm;
        float* p    = sm + 64;
        float* red  = sm + 320;
        float* vacc = sm + 336;
        __shared__ int amlast;

        if (tid < HD) q[tid] = Q[(bbase + LM1) * HD + tid];
        __syncthreads();

        const int j = c * TQ_CHUNKS + tid;
        const float* kr = K + (bbase + j) * HD;
        float dot = 0.0f;
        #pragma unroll
        for (int d = 0; d < HD; d += 4) {
            float4 k4 = *reinterpret_cast<const float4*>(kr + d);
            dot += q[d] * k4.x + q[d + 1] * k4.y + q[d + 2] * k4.z + q[d + 3] * k4.w;
        }
        dot *= scale;

        float m = dot;
        #pragma unroll
        for (int o = 16; o >= 1; o >>= 1)
            m = fmaxf(m, __shfl_xor_sync(0xffffffffu, m, o));
        if ((tid & 31) == 0) red[tid >> 5] = m;
        __syncthreads();
        m = red[0];
        #pragma unroll
        for (int w = 1; w < 8; w++) m = fmaxf(m, red[w]);

        float pv = __expf(dot - m);
        p[tid] = pv;

        float s = pv;
        #pragma unroll
        for (int o = 16; o >= 1; o >>= 1)
            s += __shfl_xor_sync(0xffffffffu, s, o);
        if ((tid & 31) == 0) red[8 + (tid >> 5)] = s;
        __syncthreads();
        s = red[8];
        #pragma unroll
        for (int w = 1; w < 8; w++) s += red[8 + w];

        const int d = tid & 63, h = tid >> 6;
        float a = 0.0f;
        #pragma unroll 8
        for (int jj = h * 64; jj < h * 64 + 64; jj++)
            a += p[jj] * V[(bbase + c * TQ_CHUNKS + jj) * HD + d];
        vacc[h * HD + d] = a;
        __syncthreads();

        float* out = g_tq + (b * TQ_NCH + c) * (HD + 2);
        if (tid < HD)
            out[tid] = vacc[tid] + vacc[HD + tid] + vacc[2 * HD + tid] + vacc[3 * HD + tid];
        else if (tid == HD) { out[HD] = m; out[HD + 1] = s; }
        __syncthreads();

        __threadfence();
        if (tid == 0) amlast = (atomicAdd(&g_tqcnt[b], 1) == TQ_NCH - 1);
        __syncthreads();
        if (!amlast) return;
        __threadfence();

        if (tid < HD) {
            const float* part = g_tq + b * TQ_NCH * (HD + 2);
            float M = -INFINITY;
            #pragma unroll
            for (int cc = 0; cc < TQ_NCH; cc++)
                M = fmaxf(M, part[cc * (HD + 2) + HD]);
            float stot = 0.0f, a2 = 0.0f;
            #pragma unroll
            for (int cc = 0; cc < TQ_NCH; cc++) {
                float f = __expf(part[cc * (HD + 2) + HD] - M);
                stot += part[cc * (HD + 2) + HD + 1] * f;
                a2   += part[cc * (HD + 2) + tid] * f;
            }
            Out[(bbase + LM1) * HD + tid] = a2 / stot;
        }
        return;
    }

    // ===================== attention path =====================
    float* Qs = sm;                      // [64][PADS] row-major, scaled tf32
    float* Ks = Qs + 64 * PADS;          // [64][PADS] tf32
    float* Vs = Ks + 64 * PADS;          // [64][PADS] tf32
    float* St = Vs + 64 * PADS;          // [64][PADS] scores / probs
    float* kt = St + 64 * PADS;          // [64] exact time key
    float* vt = kt + 64;                 // [64] exact time value
    float* frow_s = vt + 64;             // [64] per-row rescale
    float* ft_s   = frow_s + 64;
    float* pt_s   = ft_s + 64;
    float* li_s   = pt_s + 64;
    int*   klabs  = (int*)(li_s + 64);   // [64]

    const unsigned* Qu = (const unsigned*)Qs;
    const unsigned* Ku = (const unsigned*)Ks;
    const unsigned* Vu = (const unsigned*)Vs;
    const unsigned* Su = (const unsigned*)St;

    const int4 blk = g_btab[b * MAXBLK + slot];
    const int q0 = blk.x, qe = blk.y, kb = blk.z, ke = blk.w;

    const int tx = tid & 15;
    const int ty = tid >> 4;
    const int lane = tid & 31;
    const int warp = tid >> 5;
    const int mw = 16 * (warp >> 1);     // warp's m-slab (0/16/32/48)
    const int nw = 32 * (warp & 1);      // warp's n-half (0/32)
    const int gid = lane >> 2;
    const int tig = lane & 3;
    const int rA0 = (mw + gid) * PADS;
    const int rA1 = (mw + gid + 8) * PADS;

    const int* perm = g_perm + b * LSEQ;
    const int* slab = g_slab + b * LSEQ;
    const float* Kb = g_Ks + b * LSEQ * HD;
    const float* Vb = g_Vs + b * LSEQ * HD;

    // ---- stage Q (row-major, scaled, tf32) + exact time K/V
    #pragma unroll
    for (int idx = tid; idx < BM * HD; idx += NTHREADS) {
        int m = idx >> 6, d = idx & 63;
        int src = perm[min(q0 + m, LM1)];
        float v = Q[(bbase + src) * HD + d] * scale;
        Qs[m * PADS + d] = __uint_as_float(f2tf32(v));
    }
    if (tid < HD) kt[tid] = K[(bbase + LM1) * HD + tid];
    else if (tid < 2 * HD) vt[tid - HD] = V[(bbase + LM1) * HD + (tid - HD)];
    __syncthreads();

    // ---- hoist Q fragments (tile-invariant) into registers
    unsigned aq[8][4];
    #pragma unroll
    for (int kg = 0; kg < 8; kg++) {
        int k0 = kg * 8;
        aq[kg][0] = Qu[rA0 + k0 + tig];
        aq[kg][1] = Qu[rA1 + k0 + tig];
        aq[kg][2] = Qu[rA0 + k0 + tig + 4];
        aq[kg][3] = Qu[rA1 + k0 + tig + 4];
    }

    int qlab[4];
    #pragma unroll
    for (int i = 0; i < 4; i++) {
        int r = q0 + ty * 4 + i;
        qlab[i] = (r < qe) ? slab[r] : -3;
    }

    float mrow[4], lrow[4];
    #pragma unroll
    for (int i = 0; i < 4; i++) { mrow[i] = -INFINITY; lrow[i] = 0.0f; }

    float oc[4][4];
    #pragma unroll
    for (int ng = 0; ng < 4; ng++)
        #pragma unroll
        for (int r = 0; r < 4; r++) oc[ng][r] = 0.0f;

    for (int n0 = kb; n0 < ke; n0 += BN) {
        __syncthreads();   // prev PV reads done

        // ---- stage K/V tiles (rows clamped to LM1; sentinel label masks)
        #pragma unroll
        for (int idx = tid; idx < BN * 32; idx += NTHREADS) {
            int n = idx >> 5, c = (idx & 31) * 2;
            int nr = min(n0 + n, LM1);
            *(float2*)&Ks[n * PADS + c] = *(const float2*)&Kb[nr * HD + c];
            *(float2*)&Vs[n * PADS + c] = *(const float2*)&Vb[nr * HD + c];
        }
        if (tid < BN) klabs[tid] = slab[min(n0 + tid, LM1)];
        __syncthreads();

        // ---- S = Q K^T via tensor cores (conflict-free B loads, PADS=68)
        float sc[4][4];
        #pragma unroll
        for (int ng = 0; ng < 4; ng++)
            #pragma unroll
            for (int r = 0; r < 4; r++) sc[ng][r] = 0.0f;

        #pragma unroll
        for (int kg = 0; kg < 8; kg++) {
            int k0 = kg * 8;
            #pragma unroll
            for (int ng = 0; ng < 4; ng++) {
                int nb = (nw + 8 * ng + gid) * PADS + k0 + tig;
                mma_tf32(sc[ng], aq[kg][0], aq[kg][1], aq[kg][2], aq[kg][3],
                         Ku[nb], Ku[nb + 4]);
            }
        }
        #pragma unroll
        for (int ng = 0; ng < 4; ng++) {
            int cbase = nw + 8 * ng + 2 * tig;
            *(float2*)&St[rA0 + cbase] = make_float2(sc[ng][0], sc[ng][1]);
            *(float2*)&St[rA1 + cbase] = make_float2(sc[ng][2], sc[ng][3]);
        }
        __syncthreads();

        // ---- mask + online softmax (scalar path on smem S)
        int klj[4];
        #pragma unroll
        for (int j = 0; j < 4; j++) klj[j] = klabs[4 * tx + j];

        #pragma unroll
        for (int i = 0; i < 4; i++) {
            int rbase = (4 * ty + i) * PADS + 4 * tx;
            float2 lo = *(const float2*)&St[rbase];
            float2 hi = *(const float2*)&St[rbase + 2];
            float s0 = (qlab[i] == klj[0]) ? lo.x : -INFINITY;
            float s1 = (qlab[i] == klj[1]) ? lo.y : -INFINITY;
            float s2 = (qlab[i] == klj[2]) ? hi.x : -INFINITY;
            float s3 = (qlab[i] == klj[3]) ? hi.y : -INFINITY;

            float tm = fmaxf(fmaxf(s0, s1), fmaxf(s2, s3));
            #pragma unroll
            for (int o = 8; o >= 1; o >>= 1)
                tm = fmaxf(tm, __shfl_xor_sync(0xffffffffu, tm, o));

            float newm = fmaxf(mrow[i], tm);
            float mref = (newm == -INFINITY) ? 0.0f : newm;
            float fi = __expf(mrow[i] - mref);

            float p0 = __expf(s0 - mref);
            float p1 = __expf(s1 - mref);
            float p2 = __expf(s2 - mref);
            float p3 = __expf(s3 - mref);
            float rs = (p0 + p1) + (p2 + p3);
            #pragma unroll
            for (int o = 8; o >= 1; o >>= 1)
                rs += __shfl_xor_sync(0xffffffffu, rs, o);

            lrow[i] = lrow[i] * fi + rs;
            mrow[i] = newm;

            *(float2*)&St[rbase] = make_float2(__uint_as_float(f2tf32(p0)),
                                               __uint_as_float(f2tf32(p1)));
            *(float2*)&St[rbase + 2] = make_float2(__uint_as_float(f2tf32(p2)),
                                                   __uint_as_float(f2tf32(p3)));
            if (tx == 0) frow_s[4 * ty + i] = fi;
        }
        __syncthreads();

        // ---- O = O*f + P V via tensor cores (conflict-free V loads)
        {
            float f0 = frow_s[mw + gid];
            float f1 = frow_s[mw + gid + 8];
            #pragma unroll
            for (int ng = 0; ng < 4; ng++) {
                oc[ng][0] *= f0; oc[ng][1] *= f0;
                oc[ng][2] *= f1; oc[ng][3] *= f1;
            }
        }
        #pragma unroll
        for (int kg = 0; kg < 8; kg++) {
            int k0 = kg * 8;
            unsigned a0 = Su[rA0 + k0 + tig];
            unsigned a1 = Su[rA1 + k0 + tig];
            unsigned a2 = Su[rA0 + k0 + tig + 4];
            unsigned a3 = Su[rA1 + k0 + tig + 4];
            #pragma unroll
            for (int ng = 0; ng < 4; ng++) {
                int vb = (k0 + tig) * PADS + nw + 8 * ng + gid;
                mma_tf32(oc[ng], a0, a1, a2, a3, Vu[vb], Vu[vb + 4 * PADS]);
            }
        }
    }

    // ---- time key column (exact fp32)
    #pragma unroll
    for (int i = 0; i < 4; i++) {
        int row = 4 * ty + i;
        float part = 0.0f;
        #pragma unroll
        for (int jj = 0; jj < 4; jj++)
            part += Qs[row * PADS + 4 * tx + jj] * kt[4 * tx + jj];
        #pragma unroll
        for (int o = 8; o >= 1; o >>= 1)
            part += __shfl_xor_sync(0xffffffffu, part, o);
        float st = part;   // Q pre-scaled

        float newm = fmaxf(mrow[i], st);
        float f = __expf(mrow[i] - newm);
        float p = __expf(st - newm);
        lrow[i] = lrow[i] * f + p;
        mrow[i] = newm;
        if (tx == 0) {
            ft_s[row] = f;
            pt_s[row] = p;
            li_s[row] = 1.0f / lrow[i];
        }
    }
    __syncthreads();

    // ---- epilogue on O frags: time-key add, normalize, scatter
    {
        float f0 = ft_s[mw + gid],     p0 = pt_s[mw + gid],     i0 = li_s[mw + gid];
        float f1 = ft_s[mw + gid + 8], p1 = pt_s[mw + gid + 8], i1 = li_s[mw + gid + 8];
        int r0 = q0 + mw + gid;
        int r1 = r0 + 8;
        bool good0 = r0 < qe, good1 = r1 < qe;
        long long o0 = good0 ? (bbase + perm[r0]) * HD : 0;
        long long o1 = good1 ? (bbase + perm[r1]) * HD : 0;

        #pragma unroll
        for (int ng = 0; ng < 4; ng++) {
            int col = nw + 8 * ng + 2 * tig;
            float x0 = (oc[ng][0] * f0 + p0 * vt[col])     * i0;
            float x1 = (oc[ng][1] * f0 + p0 * vt[col + 1]) * i0;
            float x2 = (oc[ng][2] * f1 + p1 * vt[col])     * i1;
            float x3 = (oc[ng][3] * f1 + p1 * vt[col + 1]) * i1;
            if (good0) *(float2*)&Out[o0 + col] = make_float2(x0, x1);
            if (good1) *(float2*)&Out[o1 + col] = make_float2(x2, x3);
        }
    }
}

// ---------------------------------------------------------------------------
extern "C" void kernel_launch(void* const* d_in, const int* in_sizes, int n_in,
                              void* d_out, int out_size)
{
    const float* Q = (const float*)d_in[0];
    const float* K = (const float*)d_in[1];
    const float* V = (const float*)d_in[2];
    const int* lab = (const int*)d_in[3];
    float* Out = (float*)d_out;

    const int B = in_sizes[0] / (LSEQ * HD);

    const int sort_dyn = 2 * LSEQ * (int)sizeof(int);   // 32 KB
    cudaFuncSetAttribute(sort_kernel,
                         cudaFuncAttributeMaxDynamicSharedMemorySize, sort_dyn);
    sort_kernel<<<B, 256, sort_dyn>>>(lab);

    gather_kernel<<<B * 256, 256>>>(K, V);

    const int smem_bytes = (4 * 64 * PADS + 7 * 64) * (int)sizeof(float)
                           + 64 * (int)sizeof(int);
    cudaFuncSetAttribute(clustered_attn_kernel,
                         cudaFuncAttributeMaxDynamicSharedMemorySize, smem_bytes);
    clustered_attn_kernel<<<GRIDX * B, NTHREADS, smem_bytes>>>(Q, K, V, Out, B);
}